// round 6
// baseline (speedup 1.0000x reference)
#include <cuda_runtime.h>
#include <cuda_bf16.h>

#define NN 4096
#define BB 2
#define CC 64
#define MSPLIT 4

typedef unsigned int u32;

// Scratch
__device__ __nv_bfloat16 g_qh[(size_t)BB * NN * 8];           // [b][n][8c]
__device__ __nv_bfloat16 g_kh[(size_t)BB * NN * 8];           // [b][m][8c]
__device__ __nv_bfloat16 g_vh[(size_t)BB * CC * NN];          // [b][c][m]
__device__ __nv_bfloat16 g_po[(size_t)MSPLIT * BB * CC * NN]; // partial O [s][b][c][n]
__device__ float g_prs[(size_t)MSPLIT * BB * NN];             // partial rowsum [s][b][n]
__device__ int g_tk[BB * 64];                                 // tickets (mod-MSPLIT)

__device__ __forceinline__ u32 packbf(float lo, float hi) {
    unsigned short a = __bfloat16_as_ushort(__float2bfloat16_rn(lo));
    unsigned short b = __bfloat16_as_ushort(__float2bfloat16_rn(hi));
    return (u32)a | ((u32)b << 16);
}
__device__ __forceinline__ float2 unpackbf(u32 v) {
    __nv_bfloat162 h = *(__nv_bfloat162*)&v;
    return make_float2(__bfloat162float(h.x), __bfloat162float(h.y));
}

__device__ __forceinline__ void mma_bf16_k8(float d[4], u32 a0, u32 a1, u32 b0) {
    asm("mma.sync.aligned.m16n8k8.row.col.f32.bf16.bf16.f32 "
        "{%0,%1,%2,%3}, {%4,%5}, {%6}, {%0,%1,%2,%3};"
        : "+f"(d[0]), "+f"(d[1]), "+f"(d[2]), "+f"(d[3])
        : "r"(a0), "r"(a1), "r"(b0));
}
__device__ __forceinline__ void mma_bf16_k16(float d[4], u32 a0, u32 a1, u32 a2, u32 a3,
                                             u32 b0, u32 b1) {
    asm("mma.sync.aligned.m16n8k16.row.col.f32.bf16.bf16.f32 "
        "{%0,%1,%2,%3}, {%4,%5,%6,%7}, {%8,%9}, {%0,%1,%2,%3};"
        : "+f"(d[0]), "+f"(d[1]), "+f"(d[2]), "+f"(d[3])
        : "r"(a0), "r"(a1), "r"(a2), "r"(a3), "r"(b0), "r"(b1));
}

// ---------------------------------------------------------------------------
// Fused projection kernel, ONE launch, 512 CTAs.
//   CTAs [0,256):   q/k for a 32-column tile (2 output rows per thread).
//   CTAs [256,512): v   for a 32-column tile (4c x 2m per thread).
// ---------------------------------------------------------------------------
__global__ __launch_bounds__(256) void proj_kernel(const float* __restrict__ x,
                                                   const float* __restrict__ ctx,
                                                   const float* __restrict__ Wq,
                                                   const float* __restrict__ bq,
                                                   const float* __restrict__ Wk,
                                                   const float* __restrict__ bk,
                                                   const float* __restrict__ Wv,
                                                   const float* __restrict__ bv) {
    const int tid = threadIdx.x;
    const int role = blockIdx.x >> 8;
    const int idx = blockIdx.x & 255;
    const int b = idx >> 7;
    const int n0 = (idx & 127) * 32;

    if (role == 0) {
        // ---- q/k ----
        __shared__ float sx[64][36];
        __shared__ float sct[64][36];
        __shared__ float sW[16][64];
        __shared__ float sb[16];

        for (int i = tid; i < 512; i += 256) {
            sW[i >> 6][i & 63] = Wq[i];
            sW[8 + (i >> 6)][i & 63] = Wk[i];
        }
        if (tid < 8) { sb[tid] = bq[tid]; sb[8 + tid] = bk[tid]; }
#pragma unroll
        for (int k = 0; k < 2; k++) {
            int i = k * 256 + tid;
            int r = i >> 3, f4 = (i & 7) * 4;
            *(float4*)&sx[r][f4] = *(const float4*)&x[((size_t)b * CC + r) * NN + n0 + f4];
            *(float4*)&sct[r][f4] = *(const float4*)&ctx[((size_t)b * CC + r) * NN + n0 + f4];
        }
        __syncthreads();

        const int n = tid & 31;
        const int og = tid >> 5;          // 0..3 q row-pairs, 4..7 k row-pairs
        const bool isk = og >= 4;
        const int r2 = 2 * (og & 3);
        const int wrow = (isk ? 8 : 0) + r2;
        float a0 = sb[wrow], a1 = sb[wrow + 1];
#pragma unroll
        for (int c = 0; c < 64; c++) {
            float v = isk ? sct[c][n] : sx[c][n];
            a0 = fmaf(sW[wrow][c], v, a0);
            a1 = fmaf(sW[wrow + 1][c], v, a1);
        }
        __nv_bfloat16* dst = isk ? g_kh : g_qh;
        *(u32*)(dst + ((size_t)b * NN + n0 + n) * 8 + r2) = packbf(a0, a1);
    } else {
        // ---- v ----
        __shared__ float sC[64][36];
        __shared__ float sWv[64][68];      // [cc][c]
        __shared__ float sbv[64];

        for (int i = tid; i < 4096; i += 256) sWv[i & 63][i >> 6] = Wv[i];
        if (tid < 64) sbv[tid] = bv[tid];
#pragma unroll
        for (int k = 0; k < 2; k++) {
            int i = k * 256 + tid;
            int r = i >> 3, f4 = (i & 7) * 4;
            *(float4*)&sC[r][f4] = *(const float4*)&ctx[((size_t)b * CC + r) * NN + n0 + f4];
        }
        __syncthreads();

        const int m2 = (tid & 15) * 2;
        const int cg = (tid >> 4) * 4;
        float acc[4][2];
#pragma unroll
        for (int j = 0; j < 4; j++) acc[j][0] = acc[j][1] = sbv[cg + j];
#pragma unroll
        for (int cc = 0; cc < 64; cc++) {
            float2 vm = *(const float2*)&sC[cc][m2];
            float4 wv = *(const float4*)&sWv[cc][cg];
            float ww[4] = {wv.x, wv.y, wv.z, wv.w};
#pragma unroll
            for (int j = 0; j < 4; j++) {
                acc[j][0] = fmaf(ww[j], vm.x, acc[j][0]);
                acc[j][1] = fmaf(ww[j], vm.y, acc[j][1]);
            }
        }
#pragma unroll
        for (int j = 0; j < 4; j++)
            *(u32*)(g_vh + ((size_t)b * CC + cg + j) * NN + n0 + m2) = packbf(acc[j][0], acc[j][1]);
    }
}

// ---------------------------------------------------------------------------
// Attention: bf16 mma, P-in-register, MSPLIT=4 partials, fused combine.
//   grid (64 qtiles, B, 4), 256 threads = 8 warps, target 3 CTAs/SM.
//   sO aliases the sV double-buffer (dead after last chunk barrier).
// ---------------------------------------------------------------------------
__global__ __launch_bounds__(256, 3) void attn_kernel(const float* __restrict__ x,
                                                      const float* __restrict__ gammap,
                                                      float* __restrict__ out) {
    __shared__ __nv_bfloat16 sQ[64][8];
    __shared__ __nv_bfloat16 sK[2][64][8];
    __shared__ __align__(16) char svbuf[2][64 * 144];   // sV double buffer / sO alias
    __shared__ float sRS[64][2];
    __shared__ float sInv[64];
    __shared__ int sFlag;
    float (*sO)[65] = (float (*)[65])svbuf;

    const int tid = threadIdx.x;
    const int b = blockIdx.y;
    const int q0 = blockIdx.x * 64;
    const int s = blockIdx.z;
    const int ck0 = s * 16;
    const int w = tid >> 5;
    const int lane = tid & 31;
    const int g = lane >> 2;
    const int t = lane & 3;
    const int qT = w & 3;
    const int h = w >> 2;
    const int r = 16 * qT + g;

    const char* gk = (const char*)g_kh + (size_t)b * NN * 8 * 2;
    const char* gv = (const char*)g_vh + (size_t)b * CC * NN * 2;

    ((u32*)sQ)[tid] = ((const u32*)((const char*)g_qh + ((size_t)b * NN + q0) * 16))[tid];

    // Prefetch + commit chunk ck0 into buffer 0
    u32 kreg;
    uint4 vreg0, vreg1;
    {
        int m0 = ck0 * 64;
        kreg = *(const u32*)(gk + (size_t)m0 * 16 + tid * 4);
        const char* vb = gv + ((size_t)(tid >> 2) * NN + m0) * 2 + (tid & 3) * 32;
        vreg0 = *(const uint4*)(vb);
        vreg1 = *(const uint4*)(vb + 16);
    }
    ((u32*)sK[0])[tid] = kreg;
    {
        char* dst = svbuf[0] + (tid >> 2) * 144 + (tid & 3) * 32;
        *(uint4*)dst = vreg0;
        *(uint4*)(dst + 16) = vreg1;
    }
    __syncthreads();

    const u32 qa0 = *(const u32*)((const char*)sQ + r * 16 + t * 4);
    const u32 qa1 = *(const u32*)((const char*)sQ + (r + 8) * 16 + t * 4);

    float oC[8][4];
#pragma unroll
    for (int i = 0; i < 8; i++)
#pragma unroll
        for (int j = 0; j < 4; j++) oC[i][j] = 0.0f;
    float rs0 = 0.0f, rs1 = 0.0f;

    for (int ck = 0; ck < 16; ck++) {
        const int buf = ck & 1;

        if (ck < 15) {
            int m0 = (ck0 + ck + 1) * 64;
            kreg = *(const u32*)(gk + (size_t)m0 * 16 + tid * 4);
            const char* vb = gv + ((size_t)(tid >> 2) * NN + m0) * 2 + (tid & 3) * 32;
            vreg0 = *(const uint4*)(vb);
            vreg1 = *(const uint4*)(vb + 16);
        }

        // ---- fused S + exp + O, all in registers ----
#pragma unroll
        for (int ks = 0; ks < 2; ks++) {
            float e0[4] = {0.0f, 0.0f, 0.0f, 0.0f};
            float e1[4] = {0.0f, 0.0f, 0.0f, 0.0f};
            const int mc0 = 32 * h + 16 * ks + g;
            u32 kb0 = *(const u32*)((const char*)sK[buf] + mc0 * 16 + t * 4);
            u32 kb1 = *(const u32*)((const char*)sK[buf] + (mc0 + 8) * 16 + t * 4);
            mma_bf16_k8(e0, qa0, qa1, kb0);
            mma_bf16_k8(e1, qa0, qa1, kb1);

            float p00 = __expf(e0[0]), p01 = __expf(e0[1]);
            float p02 = __expf(e0[2]), p03 = __expf(e0[3]);
            float p10 = __expf(e1[0]), p11 = __expf(e1[1]);
            float p12 = __expf(e1[2]), p13 = __expf(e1[3]);
            rs0 += p00 + p01 + p10 + p11;
            rs1 += p02 + p03 + p12 + p13;
            u32 a0 = packbf(p00, p01);
            u32 a1 = packbf(p02, p03);
            u32 a2 = packbf(p10, p11);
            u32 a3 = packbf(p12, p13);

            const int mA = 32 * h + 16 * ks + 2 * t;
#pragma unroll
            for (int cT = 0; cT < 8; cT++) {
                int c = 8 * cT + g;
                u32 b0 = *(const u32*)(svbuf[buf] + c * 144 + mA * 2);
                u32 b1 = *(const u32*)(svbuf[buf] + c * 144 + (mA + 8) * 2);
                mma_bf16_k16(oC[cT], a0, a1, a2, a3, b0, b1);
            }
        }

        if (ck < 15) {
            ((u32*)sK[buf ^ 1])[tid] = kreg;
            char* dst = svbuf[buf ^ 1] + (tid >> 2) * 144 + (tid & 3) * 32;
            *(uint4*)dst = vreg0;
            *(uint4*)(dst + 16) = vreg1;
        }
        __syncthreads();
    }

    // Rowsums
    rs0 += __shfl_xor_sync(0xffffffffu, rs0, 1);
    rs0 += __shfl_xor_sync(0xffffffffu, rs0, 2);
    rs1 += __shfl_xor_sync(0xffffffffu, rs1, 1);
    rs1 += __shfl_xor_sync(0xffffffffu, rs1, 2);
    if (t == 0) {
        sRS[r][h] = rs0;
        sRS[r + 8][h] = rs1;
    }
    __syncthreads();   // sV buffers dead; sO may now be written

    // Cross-h O reduce into sO
    if (h == 0) {
#pragma unroll
        for (int cT = 0; cT < 8; cT++) {
            int c = 8 * cT + 2 * t;
            sO[r][c] = oC[cT][0];
            sO[r][c + 1] = oC[cT][1];
            sO[r + 8][c] = oC[cT][2];
            sO[r + 8][c + 1] = oC[cT][3];
        }
    }
    __syncthreads();
    if (h == 1) {
#pragma unroll
        for (int cT = 0; cT < 8; cT++) {
            int c = 8 * cT + 2 * t;
            sO[r][c] += oC[cT][0];
            sO[r][c + 1] += oC[cT][1];
            sO[r + 8][c] += oC[cT][2];
            sO[r + 8][c + 1] += oC[cT][3];
        }
    }
    __syncthreads();

    // Partial rowsum + partial bf16 O [s][b][c][n]
    if (tid < 64)
        g_prs[((size_t)s * BB + b) * NN + q0 + tid] = sRS[tid][0] + sRS[tid][1];
    {
        u32* po = (u32*)g_po + ((size_t)s * BB + b) * (CC * NN / 2);
#pragma unroll
        for (int k = 0; k < 8; k++) {
            int i = k * 256 + tid;
            int c = i >> 5, n2 = i & 31;
            po[(size_t)c * (NN / 2) + q0 / 2 + n2] = packbf(sO[2 * n2][c], sO[2 * n2 + 1][c]);
        }
    }

    // Ticket: the MSPLIT-th CTA of this (tile, b) performs the combine
    __threadfence();
    __syncthreads();
    if (tid == 0) sFlag = ((atomicAdd(&g_tk[b * 64 + blockIdx.x], 1) & (MSPLIT - 1)) == MSPLIT - 1);
    __syncthreads();

    if (sFlag) {
        __threadfence();
        if (tid < 64) {
            float rsum = 0.0f;
#pragma unroll
            for (int ss = 0; ss < MSPLIT; ss++)
                rsum += g_prs[((size_t)ss * BB + b) * NN + q0 + tid];
            sInv[tid] = gammap[0] / rsum;
        }
        __syncthreads();
#pragma unroll
        for (int k = 0; k < 8; k++) {
            int i = k * 256 + tid;
            int c = i >> 5, n2 = i & 31;
            size_t pi = (size_t)c * (NN / 2) + q0 / 2 + n2;
            float vx = 0.0f, vy = 0.0f;
#pragma unroll
            for (int ss = 0; ss < MSPLIT; ss++) {
                float2 v = unpackbf(((const u32*)g_po + ((size_t)ss * BB + b) * (CC * NN / 2))[pi]);
                vx += v.x;
                vy += v.y;
            }
            size_t gi = ((size_t)b * CC + c) * NN + q0 + 2 * n2;
            float2 xv = *(const float2*)&x[gi];
            float2 res;
            res.x = fmaf(vx, sInv[2 * n2], xv.x);
            res.y = fmaf(vy, sInv[2 * n2 + 1], xv.y);
            *(float2*)&out[gi] = res;
        }
    }
}

extern "C" void kernel_launch(void* const* d_in, const int* in_sizes, int n_in,
                              void* d_out, int out_size) {
    const float* x     = (const float*)d_in[0];
    const float* ctx   = (const float*)d_in[1];
    const float* Wq    = (const float*)d_in[2];
    const float* bq    = (const float*)d_in[3];
    const float* Wk    = (const float*)d_in[4];
    const float* bk    = (const float*)d_in[5];
    const float* Wv    = (const float*)d_in[6];
    const float* bv    = (const float*)d_in[7];
    const float* gamma = (const float*)d_in[8];
    float* out = (float*)d_out;

    proj_kernel<<<512, 256>>>(x, ctx, Wq, bq, Wk, bk, Wv, bv);
    attn_kernel<<<dim3(64, BB, MSPLIT), 256>>>(x, gamma, out);
}

// round 7
// speedup vs baseline: 1.1291x; 1.1291x over previous
#include <cuda_runtime.h>
#include <cuda_bf16.h>

#define NN 4096
#define BB 2
#define CC 64
#define MSPLIT 2

typedef unsigned int u32;

// Scratch
__device__ __nv_bfloat16 g_qh[(size_t)BB * NN * 8];           // [b][n][8c]
__device__ __nv_bfloat16 g_kh[(size_t)BB * NN * 8];           // [b][m][8c]
__device__ __nv_bfloat16 g_vh[(size_t)BB * CC * NN];          // [b][c][m]
__device__ __nv_bfloat16 g_po[(size_t)MSPLIT * BB * CC * NN]; // partial O [s][b][c][n]
__device__ float g_prs[(size_t)MSPLIT * BB * NN];             // partial rowsum [s][b][n]
__device__ int g_tk[BB * 64];                                 // tickets (mod-MSPLIT)

__device__ __forceinline__ u32 packbf(float lo, float hi) {
    unsigned short a = __bfloat16_as_ushort(__float2bfloat16_rn(lo));
    unsigned short b = __bfloat16_as_ushort(__float2bfloat16_rn(hi));
    return (u32)a | ((u32)b << 16);
}
__device__ __forceinline__ float2 unpackbf(u32 v) {
    __nv_bfloat162 h = *(__nv_bfloat162*)&v;
    return make_float2(__bfloat162float(h.x), __bfloat162float(h.y));
}

__device__ __forceinline__ void mma_bf16_k8(float d[4], u32 a0, u32 a1, u32 b0) {
    asm("mma.sync.aligned.m16n8k8.row.col.f32.bf16.bf16.f32 "
        "{%0,%1,%2,%3}, {%4,%5}, {%6}, {%0,%1,%2,%3};"
        : "+f"(d[0]), "+f"(d[1]), "+f"(d[2]), "+f"(d[3])
        : "r"(a0), "r"(a1), "r"(b0));
}
__device__ __forceinline__ void mma_bf16_k16(float d[4], u32 a0, u32 a1, u32 a2, u32 a3,
                                             u32 b0, u32 b1) {
    asm("mma.sync.aligned.m16n8k16.row.col.f32.bf16.bf16.f32 "
        "{%0,%1,%2,%3}, {%4,%5,%6,%7}, {%8,%9}, {%0,%1,%2,%3};"
        : "+f"(d[0]), "+f"(d[1]), "+f"(d[2]), "+f"(d[3])
        : "r"(a0), "r"(a1), "r"(a2), "r"(a3), "r"(b0), "r"(b1));
}
__device__ __forceinline__ void ldsm_x4(u32& r0, u32& r1, u32& r2, u32& r3, u32 saddr) {
    asm volatile("ldmatrix.sync.aligned.m8n8.x4.shared.b16 {%0,%1,%2,%3}, [%4];"
                 : "=r"(r0), "=r"(r1), "=r"(r2), "=r"(r3) : "r"(saddr));
}

// ---------------------------------------------------------------------------
// Fused projection kernel, ONE launch, 512 CTAs.
// ---------------------------------------------------------------------------
__global__ __launch_bounds__(256) void proj_kernel(const float* __restrict__ x,
                                                   const float* __restrict__ ctx,
                                                   const float* __restrict__ Wq,
                                                   const float* __restrict__ bq,
                                                   const float* __restrict__ Wk,
                                                   const float* __restrict__ bk,
                                                   const float* __restrict__ Wv,
                                                   const float* __restrict__ bv) {
    const int tid = threadIdx.x;
    const int role = blockIdx.x >> 8;
    const int idx = blockIdx.x & 255;
    const int b = idx >> 7;
    const int n0 = (idx & 127) * 32;

    if (role == 0) {
        __shared__ float sx[64][36];
        __shared__ float sct[64][36];
        __shared__ float sW[16][64];
        __shared__ float sb[16];

        for (int i = tid; i < 512; i += 256) {
            sW[i >> 6][i & 63] = Wq[i];
            sW[8 + (i >> 6)][i & 63] = Wk[i];
        }
        if (tid < 8) { sb[tid] = bq[tid]; sb[8 + tid] = bk[tid]; }
#pragma unroll
        for (int k = 0; k < 2; k++) {
            int i = k * 256 + tid;
            int r = i >> 3, f4 = (i & 7) * 4;
            *(float4*)&sx[r][f4] = *(const float4*)&x[((size_t)b * CC + r) * NN + n0 + f4];
            *(float4*)&sct[r][f4] = *(const float4*)&ctx[((size_t)b * CC + r) * NN + n0 + f4];
        }
        __syncthreads();

        const int n = tid & 31;
        const int og = tid >> 5;
        const bool isk = og >= 4;
        const int r2 = 2 * (og & 3);
        const int wrow = (isk ? 8 : 0) + r2;
        float a0 = sb[wrow], a1 = sb[wrow + 1];
#pragma unroll
        for (int c = 0; c < 64; c++) {
            float v = isk ? sct[c][n] : sx[c][n];
            a0 = fmaf(sW[wrow][c], v, a0);
            a1 = fmaf(sW[wrow + 1][c], v, a1);
        }
        __nv_bfloat16* dst = isk ? g_kh : g_qh;
        *(u32*)(dst + ((size_t)b * NN + n0 + n) * 8 + r2) = packbf(a0, a1);
    } else {
        __shared__ float sC[64][36];
        __shared__ float sWv[64][68];
        __shared__ float sbv[64];

        for (int i = tid; i < 4096; i += 256) sWv[i & 63][i >> 6] = Wv[i];
        if (tid < 64) sbv[tid] = bv[tid];
#pragma unroll
        for (int k = 0; k < 2; k++) {
            int i = k * 256 + tid;
            int r = i >> 3, f4 = (i & 7) * 4;
            *(float4*)&sC[r][f4] = *(const float4*)&ctx[((size_t)b * CC + r) * NN + n0 + f4];
        }
        __syncthreads();

        const int m2 = (tid & 15) * 2;
        const int cg = (tid >> 4) * 4;
        float acc[4][2];
#pragma unroll
        for (int j = 0; j < 4; j++) acc[j][0] = acc[j][1] = sbv[cg + j];
#pragma unroll
        for (int cc = 0; cc < 64; cc++) {
            float2 vm = *(const float2*)&sC[cc][m2];
            float4 wv = *(const float4*)&sWv[cc][cg];
            float ww[4] = {wv.x, wv.y, wv.z, wv.w};
#pragma unroll
            for (int j = 0; j < 4; j++) {
                acc[j][0] = fmaf(ww[j], vm.x, acc[j][0]);
                acc[j][1] = fmaf(ww[j], vm.y, acc[j][1]);
            }
        }
#pragma unroll
        for (int j = 0; j < 4; j++)
            *(u32*)(g_vh + ((size_t)b * CC + cg + j) * NN + n0 + m2) = packbf(acc[j][0], acc[j][1]);
    }
}

// ---------------------------------------------------------------------------
// Attention: bf16 mma, P-in-register, ldmatrix B-frags, MSPLIT=2, fused combine.
//   grid (64 qtiles, B, 2), 256 threads = 8 warps, 2 CTAs/SM.
// ---------------------------------------------------------------------------
__global__ __launch_bounds__(256, 2) void attn_kernel(const float* __restrict__ x,
                                                      const float* __restrict__ gammap,
                                                      float* __restrict__ out) {
    __shared__ __nv_bfloat16 sQ[64][8];
    __shared__ __nv_bfloat16 sK[2][64][8];
    __shared__ __align__(16) char svbuf[2][64 * 144];   // sV double buffer / sO alias
    __shared__ float sRS[64][2];
    __shared__ float sInv[64];
    __shared__ int sFlag;
    float (*sO)[65] = (float (*)[65])svbuf;

    const int tid = threadIdx.x;
    const int b = blockIdx.y;
    const int q0 = blockIdx.x * 64;
    const int s = blockIdx.z;
    const int ck0 = s * 32;
    const int w = tid >> 5;
    const int lane = tid & 31;
    const int g = lane >> 2;
    const int t = lane & 3;
    const int qT = w & 3;
    const int h = w >> 2;
    const int r = 16 * qT + g;

    const char* gk = (const char*)g_kh + (size_t)b * NN * 8 * 2;
    const char* gv = (const char*)g_vh + (size_t)b * CC * NN * 2;

    ((u32*)sQ)[tid] = ((const u32*)((const char*)g_qh + ((size_t)b * NN + q0) * 16))[tid];

    // ldmatrix row addresses (shared-space u32)
    const u32 svb = (u32)__cvta_generic_to_shared(svbuf);
    const u32 skb = (u32)__cvta_generic_to_shared(sK);
    const u32 vA = svb + lane * 144 + 64 * h;        // c = lane,    m base 32h
    const u32 vB = vA + 32 * 144;                    // c = 32+lane
    const u32 kA = skb + (32 * h + lane) * 16;       // m = 32h+lane

    // Prefetch + commit chunk ck0 into buffer 0
    u32 kreg;
    uint4 vreg0, vreg1;
    {
        int m0 = ck0 * 64;
        kreg = *(const u32*)(gk + (size_t)m0 * 16 + tid * 4);
        const char* vb = gv + ((size_t)(tid >> 2) * NN + m0) * 2 + (tid & 3) * 32;
        vreg0 = *(const uint4*)(vb);
        vreg1 = *(const uint4*)(vb + 16);
    }
    ((u32*)sK[0])[tid] = kreg;
    {
        char* dst = svbuf[0] + (tid >> 2) * 144 + (tid & 3) * 32;
        *(uint4*)dst = vreg0;
        *(uint4*)(dst + 16) = vreg1;
    }
    __syncthreads();

    const u32 qa0 = *(const u32*)((const char*)sQ + r * 16 + t * 4);
    const u32 qa1 = *(const u32*)((const char*)sQ + (r + 8) * 16 + t * 4);

    float oC[8][4];
#pragma unroll
    for (int i = 0; i < 8; i++)
#pragma unroll
        for (int j = 0; j < 4; j++) oC[i][j] = 0.0f;
    float rs0 = 0.0f, rs1 = 0.0f;

    for (int ck = 0; ck < 32; ck++) {
        const int buf = ck & 1;
        const u32 vOff = buf * 9216;
        const u32 kOff = buf * 1024;

        if (ck < 31) {
            int m0 = (ck0 + ck + 1) * 64;
            kreg = *(const u32*)(gk + (size_t)m0 * 16 + tid * 4);
            const char* vb = gv + ((size_t)(tid >> 2) * NN + m0) * 2 + (tid & 3) * 32;
            vreg0 = *(const uint4*)(vb);
            vreg1 = *(const uint4*)(vb + 16);
        }

        // K b-frags for this chunk: 4 tiles (m blocks 32h+8i) in one ldmatrix
        u32 kb[4];
        ldsm_x4(kb[0], kb[1], kb[2], kb[3], kA + kOff);

        // ---- fused S + exp + O ----
#pragma unroll
        for (int ks = 0; ks < 2; ks++) {
            float e0[4] = {0.0f, 0.0f, 0.0f, 0.0f};
            float e1[4] = {0.0f, 0.0f, 0.0f, 0.0f};
            mma_bf16_k8(e0, qa0, qa1, kb[2 * ks]);
            mma_bf16_k8(e1, qa0, qa1, kb[2 * ks + 1]);

            // V b-frags: 16 tiles (8 cT x 2 m-halves) in 4 ldmatrix.x4
            u32 bl[4][2], bh[4][2];   // bl: cT0-3, bh: cT4-7; [cT][mhalf]
            {
                u32 base = vOff + 32 * ks;
                ldsm_x4(bl[0][0], bl[1][0], bl[2][0], bl[3][0], vA + base);
                ldsm_x4(bl[0][1], bl[1][1], bl[2][1], bl[3][1], vA + base + 16);
                ldsm_x4(bh[0][0], bh[1][0], bh[2][0], bh[3][0], vB + base);
                ldsm_x4(bh[0][1], bh[1][1], bh[2][1], bh[3][1], vB + base + 16);
            }

            float p00 = __expf(e0[0]), p01 = __expf(e0[1]);
            float p02 = __expf(e0[2]), p03 = __expf(e0[3]);
            float p10 = __expf(e1[0]), p11 = __expf(e1[1]);
            float p12 = __expf(e1[2]), p13 = __expf(e1[3]);
            rs0 += p00 + p01 + p10 + p11;
            rs1 += p02 + p03 + p12 + p13;
            u32 a0 = packbf(p00, p01);
            u32 a1 = packbf(p02, p03);
            u32 a2 = packbf(p10, p11);
            u32 a3 = packbf(p12, p13);

#pragma unroll
            for (int cT = 0; cT < 4; cT++)
                mma_bf16_k16(oC[cT], a0, a1, a2, a3, bl[cT][0], bl[cT][1]);
#pragma unroll
            for (int cT = 0; cT < 4; cT++)
                mma_bf16_k16(oC[4 + cT], a0, a1, a2, a3, bh[cT][0], bh[cT][1]);
        }

        if (ck < 31) {
            ((u32*)sK[buf ^ 1])[tid] = kreg;
            char* dst = svbuf[buf ^ 1] + (tid >> 2) * 144 + (tid & 3) * 32;
            *(uint4*)dst = vreg0;
            *(uint4*)(dst + 16) = vreg1;
        }
        __syncthreads();
    }

    // Rowsums
    rs0 += __shfl_xor_sync(0xffffffffu, rs0, 1);
    rs0 += __shfl_xor_sync(0xffffffffu, rs0, 2);
    rs1 += __shfl_xor_sync(0xffffffffu, rs1, 1);
    rs1 += __shfl_xor_sync(0xffffffffu, rs1, 2);
    if (t == 0) {
        sRS[r][h] = rs0;
        sRS[r + 8][h] = rs1;
    }
    __syncthreads();   // sV buffers dead; sO may now be written

    // Cross-h O reduce into sO
    if (h == 0) {
#pragma unroll
        for (int cT = 0; cT < 8; cT++) {
            int c = 8 * cT + 2 * t;
            sO[r][c] = oC[cT][0];
            sO[r][c + 1] = oC[cT][1];
            sO[r + 8][c] = oC[cT][2];
            sO[r + 8][c + 1] = oC[cT][3];
        }
    }
    __syncthreads();
    if (h == 1) {
#pragma unroll
        for (int cT = 0; cT < 8; cT++) {
            int c = 8 * cT + 2 * t;
            sO[r][c] += oC[cT][0];
            sO[r][c + 1] += oC[cT][1];
            sO[r + 8][c] += oC[cT][2];
            sO[r + 8][c + 1] += oC[cT][3];
        }
    }
    __syncthreads();

    // Partial rowsum + partial bf16 O [s][b][c][n]
    if (tid < 64)
        g_prs[((size_t)s * BB + b) * NN + q0 + tid] = sRS[tid][0] + sRS[tid][1];
    {
        u32* po = (u32*)g_po + ((size_t)s * BB + b) * (CC * NN / 2);
#pragma unroll
        for (int k = 0; k < 8; k++) {
            int i = k * 256 + tid;
            int c = i >> 5, n2 = i & 31;
            po[(size_t)c * (NN / 2) + q0 / 2 + n2] = packbf(sO[2 * n2][c], sO[2 * n2 + 1][c]);
        }
    }

    // Ticket: last CTA of this (tile, b) performs the combine
    __threadfence();
    __syncthreads();
    if (tid == 0) sFlag = ((atomicAdd(&g_tk[b * 64 + blockIdx.x], 1) & (MSPLIT - 1)) == MSPLIT - 1);
    __syncthreads();

    if (sFlag) {
        __threadfence();
        if (tid < 64) {
            float rsum = 0.0f;
#pragma unroll
            for (int ss = 0; ss < MSPLIT; ss++)
                rsum += g_prs[((size_t)ss * BB + b) * NN + q0 + tid];
            sInv[tid] = gammap[0] / rsum;
        }
        __syncthreads();
#pragma unroll
        for (int k = 0; k < 8; k++) {
            int i = k * 256 + tid;
            int c = i >> 5, n2 = i & 31;
            size_t pi = (size_t)c * (NN / 2) + q0 / 2 + n2;
            float vx = 0.0f, vy = 0.0f;
#pragma unroll
            for (int ss = 0; ss < MSPLIT; ss++) {
                float2 v = unpackbf(((const u32*)g_po + ((size_t)ss * BB + b) * (CC * NN / 2))[pi]);
                vx += v.x;
                vy += v.y;
            }
            size_t gi = ((size_t)b * CC + c) * NN + q0 + 2 * n2;
            float2 xv = *(const float2*)&x[gi];
            float2 res;
            res.x = fmaf(vx, sInv[2 * n2], xv.x);
            res.y = fmaf(vy, sInv[2 * n2 + 1], xv.y);
            *(float2*)&out[gi] = res;
        }
    }
}

extern "C" void kernel_launch(void* const* d_in, const int* in_sizes, int n_in,
                              void* d_out, int out_size) {
    const float* x     = (const float*)d_in[0];
    const float* ctx   = (const float*)d_in[1];
    const float* Wq    = (const float*)d_in[2];
    const float* bq    = (const float*)d_in[3];
    const float* Wk    = (const float*)d_in[4];
    const float* bk    = (const float*)d_in[5];
    const float* Wv    = (const float*)d_in[6];
    const float* bv    = (const float*)d_in[7];
    const float* gamma = (const float*)d_in[8];
    float* out = (float*)d_out;

    proj_kernel<<<512, 256>>>(x, ctx, Wq, bq, Wk, bk, Wv, bv);
    attn_kernel<<<dim3(64, BB, MSPLIT), 256>>>(x, gamma, out);
}

// round 8
// speedup vs baseline: 1.3529x; 1.1982x over previous
#include <cuda_runtime.h>
#include <cuda_bf16.h>

#define NN 4096
#define BB 2
#define CC 64
#define MSPLIT 2

typedef unsigned int u32;

// Scratch
__device__ __nv_bfloat16 g_qh[(size_t)BB * NN * 8];           // [b][n][8c] (q pre-scaled by log2e)
__device__ __nv_bfloat16 g_kh[(size_t)BB * NN * 8];           // [b][m][8c]
__device__ __nv_bfloat16 g_vh[(size_t)BB * CC * NN];          // [b][c][m]
__device__ __nv_bfloat16 g_po[(size_t)MSPLIT * BB * CC * NN]; // partial O [s][b][c][n]
__device__ float g_prs[(size_t)MSPLIT * BB * NN];             // partial rowsum [s][b][n]
__device__ int g_tk[BB * 64];                                 // tickets (mod-MSPLIT)

__device__ __forceinline__ u32 packbf(float lo, float hi) {
    u32 r;
    asm("cvt.rn.bf16x2.f32 %0, %1, %2;" : "=r"(r) : "f"(hi), "f"(lo));
    return r;
}
__device__ __forceinline__ float2 unpackbf(u32 v) {
    __nv_bfloat162 h = *(__nv_bfloat162*)&v;
    return make_float2(__bfloat162float(h.x), __bfloat162float(h.y));
}
__device__ __forceinline__ float ex2(float x) {
    float y;
    asm("ex2.approx.ftz.f32 %0, %1;" : "=f"(y) : "f"(x));
    return y;
}

__device__ __forceinline__ void mma_bf16_k8(float d[4], u32 a0, u32 a1, u32 b0) {
    asm("mma.sync.aligned.m16n8k8.row.col.f32.bf16.bf16.f32 "
        "{%0,%1,%2,%3}, {%4,%5}, {%6}, {%0,%1,%2,%3};"
        : "+f"(d[0]), "+f"(d[1]), "+f"(d[2]), "+f"(d[3])
        : "r"(a0), "r"(a1), "r"(b0));
}
__device__ __forceinline__ void mma_bf16_k16(float d[4], u32 a0, u32 a1, u32 a2, u32 a3,
                                             u32 b0, u32 b1) {
    asm("mma.sync.aligned.m16n8k16.row.col.f32.bf16.bf16.f32 "
        "{%0,%1,%2,%3}, {%4,%5,%6,%7}, {%8,%9}, {%0,%1,%2,%3};"
        : "+f"(d[0]), "+f"(d[1]), "+f"(d[2]), "+f"(d[3])
        : "r"(a0), "r"(a1), "r"(a2), "r"(a3), "r"(b0), "r"(b1));
}
__device__ __forceinline__ void ldsm_x4(u32& r0, u32& r1, u32& r2, u32& r3, u32 saddr) {
    asm volatile("ldmatrix.sync.aligned.m8n8.x4.shared.b16 {%0,%1,%2,%3}, [%4];"
                 : "=r"(r0), "=r"(r1), "=r"(r2), "=r"(r3) : "r"(saddr));
}
__device__ __forceinline__ void cp16(u32 dst, const void* src) {
    asm volatile("cp.async.cg.shared.global [%0], [%1], 16;" :: "r"(dst), "l"(src));
}
__device__ __forceinline__ void cp4(u32 dst, const void* src) {
    asm volatile("cp.async.ca.shared.global [%0], [%1], 4;" :: "r"(dst), "l"(src));
}
__device__ __forceinline__ void cp_commit() { asm volatile("cp.async.commit_group;"); }
__device__ __forceinline__ void cp_wait0() { asm volatile("cp.async.wait_group 0;"); }

// ---------------------------------------------------------------------------
// Fused projection kernel, ONE launch, 512 CTAs.
//   q rows pre-scaled by log2(e) so attention uses ex2 directly.
// ---------------------------------------------------------------------------
__global__ __launch_bounds__(256) void proj_kernel(const float* __restrict__ x,
                                                   const float* __restrict__ ctx,
                                                   const float* __restrict__ Wq,
                                                   const float* __restrict__ bq,
                                                   const float* __restrict__ Wk,
                                                   const float* __restrict__ bk,
                                                   const float* __restrict__ Wv,
                                                   const float* __restrict__ bv) {
    const int tid = threadIdx.x;
    const int role = blockIdx.x >> 8;
    const int idx = blockIdx.x & 255;
    const int b = idx >> 7;
    const int n0 = (idx & 127) * 32;
    const float LOG2E = 1.4426950408889634f;

    if (role == 0) {
        __shared__ float sx[64][36];
        __shared__ float sct[64][36];
        __shared__ float sW[16][64];
        __shared__ float sb[16];

        for (int i = tid; i < 512; i += 256) {
            sW[i >> 6][i & 63] = Wq[i] * LOG2E;
            sW[8 + (i >> 6)][i & 63] = Wk[i];
        }
        if (tid < 8) { sb[tid] = bq[tid] * LOG2E; sb[8 + tid] = bk[tid]; }
#pragma unroll
        for (int k = 0; k < 2; k++) {
            int i = k * 256 + tid;
            int r = i >> 3, f4 = (i & 7) * 4;
            *(float4*)&sx[r][f4] = *(const float4*)&x[((size_t)b * CC + r) * NN + n0 + f4];
            *(float4*)&sct[r][f4] = *(const float4*)&ctx[((size_t)b * CC + r) * NN + n0 + f4];
        }
        __syncthreads();

        const int n = tid & 31;
        const int og = tid >> 5;
        const bool isk = og >= 4;
        const int r2 = 2 * (og & 3);
        const int wrow = (isk ? 8 : 0) + r2;
        float a0 = sb[wrow], a1 = sb[wrow + 1];
#pragma unroll
        for (int c = 0; c < 64; c++) {
            float v = isk ? sct[c][n] : sx[c][n];
            a0 = fmaf(sW[wrow][c], v, a0);
            a1 = fmaf(sW[wrow + 1][c], v, a1);
        }
        __nv_bfloat16* dst = isk ? g_kh : g_qh;
        *(u32*)(dst + ((size_t)b * NN + n0 + n) * 8 + r2) = packbf(a0, a1);
    } else {
        __shared__ float sC[64][36];
        __shared__ float sWv[64][68];
        __shared__ float sbv[64];

        for (int i = tid; i < 4096; i += 256) sWv[i & 63][i >> 6] = Wv[i];
        if (tid < 64) sbv[tid] = bv[tid];
#pragma unroll
        for (int k = 0; k < 2; k++) {
            int i = k * 256 + tid;
            int r = i >> 3, f4 = (i & 7) * 4;
            *(float4*)&sC[r][f4] = *(const float4*)&ctx[((size_t)b * CC + r) * NN + n0 + f4];
        }
        __syncthreads();

        const int m2 = (tid & 15) * 2;
        const int cg = (tid >> 4) * 4;
        float acc[4][2];
#pragma unroll
        for (int j = 0; j < 4; j++) acc[j][0] = acc[j][1] = sbv[cg + j];
#pragma unroll
        for (int cc = 0; cc < 64; cc++) {
            float2 vm = *(const float2*)&sC[cc][m2];
            float4 wv = *(const float4*)&sWv[cc][cg];
            float ww[4] = {wv.x, wv.y, wv.z, wv.w};
#pragma unroll
            for (int j = 0; j < 4; j++) {
                acc[j][0] = fmaf(ww[j], vm.x, acc[j][0]);
                acc[j][1] = fmaf(ww[j], vm.y, acc[j][1]);
            }
        }
#pragma unroll
        for (int j = 0; j < 4; j++)
            *(u32*)(g_vh + ((size_t)b * CC + cg + j) * NN + n0 + m2) = packbf(acc[j][0], acc[j][1]);
    }
}

// ---------------------------------------------------------------------------
// Attention: bf16 mma, P-in-register, ldmatrix + cp.async, MSPLIT=2.
//   grid (64 qtiles, B, 2), 256 threads = 8 warps, 2 CTAs/SM.
// ---------------------------------------------------------------------------
__global__ __launch_bounds__(256, 2) void attn_kernel(const float* __restrict__ x,
                                                      const float* __restrict__ gammap,
                                                      float* __restrict__ out) {
    __shared__ __nv_bfloat16 sQ[64][8];
    __shared__ __nv_bfloat16 sK[2][64][8];
    __shared__ __align__(16) char svbuf[2][64 * 144];   // sV double buffer / sO alias
    __shared__ float sRS[64][2];
    __shared__ float sInv[64];
    __shared__ int sFlag;
    float (*sO)[65] = (float (*)[65])svbuf;

    const int tid = threadIdx.x;
    const int b = blockIdx.y;
    const int q0 = blockIdx.x * 64;
    const int s = blockIdx.z;
    const int ck0 = s * 32;
    const int w = tid >> 5;
    const int lane = tid & 31;
    const int g = lane >> 2;
    const int t = lane & 3;
    const int qT = w & 3;
    const int h = w >> 2;
    const int r = 16 * qT + g;

    const char* gk = (const char*)g_kh + (size_t)b * NN * 8 * 2;
    const char* gv = (const char*)g_vh + (size_t)b * CC * NN * 2;

    ((u32*)sQ)[tid] = ((const u32*)((const char*)g_qh + ((size_t)b * NN + q0) * 16))[tid];

    // shared-space addresses
    const u32 svb = (u32)__cvta_generic_to_shared(svbuf);
    const u32 skb = (u32)__cvta_generic_to_shared(sK);
    const u32 vA = svb + lane * 144 + 64 * h;        // ldmatrix: c = lane,    m base 32h
    const u32 vB = vA + 32 * 144;                    //           c = 32+lane
    const u32 kA = skb + (32 * h + lane) * 16;       //           m = 32h+lane
    // cp.async dst/src fixed per thread
    const u32 kDst = skb + tid * 4;
    const u32 vDst = svb + (tid >> 2) * 144 + (tid & 3) * 32;
    const char* kSrc = gk + tid * 4;
    const char* vSrc = gv + ((size_t)(tid >> 2) * NN) * 2 + (tid & 3) * 32;

    // Stage chunk ck0 into buffer 0
    {
        size_t off = (size_t)ck0 * 64;
        cp4(kDst, kSrc + off * 16);
        cp16(vDst, vSrc + off * 2);
        cp16(vDst + 16, vSrc + off * 2 + 16);
        cp_commit();
    }
    cp_wait0();
    __syncthreads();

    const u32 qa0 = *(const u32*)((const char*)sQ + r * 16 + t * 4);
    const u32 qa1 = *(const u32*)((const char*)sQ + (r + 8) * 16 + t * 4);

    float oC[8][4];
#pragma unroll
    for (int i = 0; i < 8; i++)
#pragma unroll
        for (int j = 0; j < 4; j++) oC[i][j] = 0.0f;
    float rs0 = 0.0f, rs1 = 0.0f;

    for (int ck = 0; ck < 32; ck++) {
        const int buf = ck & 1;
        const u32 vOff = buf * 9216;
        const u32 kOff = buf * 1024;

        // Stage next chunk into the other buffer (async)
        if (ck < 31) {
            size_t off = (size_t)(ck0 + ck + 1) * 64;
            const u32 nb = (buf ^ 1);
            cp4(kDst + nb * 1024, kSrc + off * 16);
            cp16(vDst + nb * 9216, vSrc + off * 2);
            cp16(vDst + nb * 9216 + 16, vSrc + off * 2 + 16);
            cp_commit();
        }

        // K b-frags: 4 tiles in one ldmatrix
        u32 kb[4];
        ldsm_x4(kb[0], kb[1], kb[2], kb[3], kA + kOff);

        // ---- fused S + exp2 + O ----
#pragma unroll
        for (int ks = 0; ks < 2; ks++) {
            float e0[4] = {0.0f, 0.0f, 0.0f, 0.0f};
            float e1[4] = {0.0f, 0.0f, 0.0f, 0.0f};
            mma_bf16_k8(e0, qa0, qa1, kb[2 * ks]);
            mma_bf16_k8(e1, qa0, qa1, kb[2 * ks + 1]);

            u32 bl[4][2], bh[4][2];
            {
                u32 base = vOff + 32 * ks;
                ldsm_x4(bl[0][0], bl[1][0], bl[2][0], bl[3][0], vA + base);
                ldsm_x4(bl[0][1], bl[1][1], bl[2][1], bl[3][1], vA + base + 16);
                ldsm_x4(bh[0][0], bh[1][0], bh[2][0], bh[3][0], vB + base);
                ldsm_x4(bh[0][1], bh[1][1], bh[2][1], bh[3][1], vB + base + 16);
            }

            float p00 = ex2(e0[0]), p01 = ex2(e0[1]);
            float p02 = ex2(e0[2]), p03 = ex2(e0[3]);
            float p10 = ex2(e1[0]), p11 = ex2(e1[1]);
            float p12 = ex2(e1[2]), p13 = ex2(e1[3]);
            rs0 += p00 + p01 + p10 + p11;
            rs1 += p02 + p03 + p12 + p13;
            u32 a0 = packbf(p00, p01);
            u32 a1 = packbf(p02, p03);
            u32 a2 = packbf(p10, p11);
            u32 a3 = packbf(p12, p13);

#pragma unroll
            for (int cT = 0; cT < 4; cT++)
                mma_bf16_k16(oC[cT], a0, a1, a2, a3, bl[cT][0], bl[cT][1]);
#pragma unroll
            for (int cT = 0; cT < 4; cT++)
                mma_bf16_k16(oC[4 + cT], a0, a1, a2, a3, bh[cT][0], bh[cT][1]);
        }

        cp_wait0();
        __syncthreads();
    }

    // Rowsums
    rs0 += __shfl_xor_sync(0xffffffffu, rs0, 1);
    rs0 += __shfl_xor_sync(0xffffffffu, rs0, 2);
    rs1 += __shfl_xor_sync(0xffffffffu, rs1, 1);
    rs1 += __shfl_xor_sync(0xffffffffu, rs1, 2);
    if (t == 0) {
        sRS[r][h] = rs0;
        sRS[r + 8][h] = rs1;
    }
    __syncthreads();   // sV buffers dead; sO may now be written

    // Cross-h O reduce into sO
    if (h == 0) {
#pragma unroll
        for (int cT = 0; cT < 8; cT++) {
            int c = 8 * cT + 2 * t;
            sO[r][c] = oC[cT][0];
            sO[r][c + 1] = oC[cT][1];
            sO[r + 8][c] = oC[cT][2];
            sO[r + 8][c + 1] = oC[cT][3];
        }
    }
    __syncthreads();
    if (h == 1) {
#pragma unroll
        for (int cT = 0; cT < 8; cT++) {
            int c = 8 * cT + 2 * t;
            sO[r][c] += oC[cT][0];
            sO[r][c + 1] += oC[cT][1];
            sO[r + 8][c] += oC[cT][2];
            sO[r + 8][c + 1] += oC[cT][3];
        }
    }
    __syncthreads();

    // Partial rowsum + partial bf16 O [s][b][c][n]
    if (tid < 64)
        g_prs[((size_t)s * BB + b) * NN + q0 + tid] = sRS[tid][0] + sRS[tid][1];
    {
        u32* po = (u32*)g_po + ((size_t)s * BB + b) * (CC * NN / 2);
#pragma unroll
        for (int k = 0; k < 8; k++) {
            int i = k * 256 + tid;
            int c = i >> 5, n2 = i & 31;
            po[(size_t)c * (NN / 2) + q0 / 2 + n2] = packbf(sO[2 * n2][c], sO[2 * n2 + 1][c]);
        }
    }

    // Ticket: last CTA of this (tile, b) performs the combine
    __threadfence();
    __syncthreads();
    if (tid == 0) sFlag = ((atomicAdd(&g_tk[b * 64 + blockIdx.x], 1) & (MSPLIT - 1)) == MSPLIT - 1);
    __syncthreads();

    if (sFlag) {
        __threadfence();
        if (tid < 64) {
            float rsum = 0.0f;
#pragma unroll
            for (int ss = 0; ss < MSPLIT; ss++)
                rsum += g_prs[((size_t)ss * BB + b) * NN + q0 + tid];
            sInv[tid] = gammap[0] / rsum;
        }
        __syncthreads();
#pragma unroll
        for (int k = 0; k < 8; k++) {
            int i = k * 256 + tid;
            int c = i >> 5, n2 = i & 31;
            size_t pi = (size_t)c * (NN / 2) + q0 / 2 + n2;
            float vx = 0.0f, vy = 0.0f;
#pragma unroll
            for (int ss = 0; ss < MSPLIT; ss++) {
                float2 v = unpackbf(((const u32*)g_po + ((size_t)ss * BB + b) * (CC * NN / 2))[pi]);
                vx += v.x;
                vy += v.y;
            }
            size_t gi = ((size_t)b * CC + c) * NN + q0 + 2 * n2;
            float2 xv = *(const float2*)&x[gi];
            float2 res;
            res.x = fmaf(vx, sInv[2 * n2], xv.x);
            res.y = fmaf(vy, sInv[2 * n2 + 1], xv.y);
            *(float2*)&out[gi] = res;
        }
    }
}

extern "C" void kernel_launch(void* const* d_in, const int* in_sizes, int n_in,
                              void* d_out, int out_size) {
    const float* x     = (const float*)d_in[0];
    const float* ctx   = (const float*)d_in[1];
    const float* Wq    = (const float*)d_in[2];
    const float* bq    = (const float*)d_in[3];
    const float* Wk    = (const float*)d_in[4];
    const float* bk    = (const float*)d_in[5];
    const float* Wv    = (const float*)d_in[6];
    const float* bv    = (const float*)d_in[7];
    const float* gamma = (const float*)d_in[8];
    float* out = (float*)d_out;

    proj_kernel<<<512, 256>>>(x, ctx, Wq, bq, Wk, bk, Wv, bv);
    attn_kernel<<<dim3(64, BB, MSPLIT), 256>>>(x, gamma, out);
}

// round 10
// speedup vs baseline: 1.3628x; 1.0073x over previous
#include <cuda_runtime.h>
#include <cuda_bf16.h>

#define NN 4096
#define BB 2
#define CC 64
#define MSPLIT 2

typedef unsigned int u32;

// Scratch
__device__ __nv_bfloat16 g_qh[(size_t)BB * NN * 8];           // [b][n][8c] (q pre-scaled by log2e)
__device__ __nv_bfloat16 g_kh[(size_t)BB * NN * 8];           // [b][m][8c]
__device__ __nv_bfloat16 g_vh[(size_t)BB * CC * NN];          // [b][c][m]
__device__ __nv_bfloat16 g_po[(size_t)MSPLIT * BB * CC * NN]; // partial O [s][b][c][n]
__device__ float g_prs[(size_t)MSPLIT * BB * NN];             // partial rowsum [s][b][n]
__device__ int g_tk[BB * 64];                                 // tickets (mod-MSPLIT)

__device__ __forceinline__ u32 packbf(float lo, float hi) {
    u32 r;
    asm("cvt.rn.bf16x2.f32 %0, %1, %2;" : "=r"(r) : "f"(hi), "f"(lo));
    return r;
}
__device__ __forceinline__ float2 unpackbf(u32 v) {
    __nv_bfloat162 h = *(__nv_bfloat162*)&v;
    return make_float2(__bfloat162float(h.x), __bfloat162float(h.y));
}
__device__ __forceinline__ float ex2(float x) {
    float y;
    asm("ex2.approx.ftz.f32 %0, %1;" : "=f"(y) : "f"(x));
    return y;
}

__device__ __forceinline__ void mma_bf16_k8(float d[4], u32 a0, u32 a1, u32 b0) {
    asm("mma.sync.aligned.m16n8k8.row.col.f32.bf16.bf16.f32 "
        "{%0,%1,%2,%3}, {%4,%5}, {%6}, {%0,%1,%2,%3};"
        : "+f"(d[0]), "+f"(d[1]), "+f"(d[2]), "+f"(d[3])
        : "r"(a0), "r"(a1), "r"(b0));
}
__device__ __forceinline__ void mma_bf16_k16(float d[4], u32 a0, u32 a1, u32 a2, u32 a3,
                                             u32 b0, u32 b1) {
    asm("mma.sync.aligned.m16n8k16.row.col.f32.bf16.bf16.f32 "
        "{%0,%1,%2,%3}, {%4,%5,%6,%7}, {%8,%9}, {%0,%1,%2,%3};"
        : "+f"(d[0]), "+f"(d[1]), "+f"(d[2]), "+f"(d[3])
        : "r"(a0), "r"(a1), "r"(a2), "r"(a3), "r"(b0), "r"(b1));
}
__device__ __forceinline__ void ldsm_x4(u32& r0, u32& r1, u32& r2, u32& r3, u32 saddr) {
    asm volatile("ldmatrix.sync.aligned.m8n8.x4.shared.b16 {%0,%1,%2,%3}, [%4];"
                 : "=r"(r0), "=r"(r1), "=r"(r2), "=r"(r3) : "r"(saddr));
}
__device__ __forceinline__ void cp16(u32 dst, const void* src) {
    asm volatile("cp.async.cg.shared.global [%0], [%1], 16;" :: "r"(dst), "l"(src));
}
__device__ __forceinline__ void cp4(u32 dst, const void* src) {
    asm volatile("cp.async.ca.shared.global [%0], [%1], 4;" :: "r"(dst), "l"(src));
}
__device__ __forceinline__ void cp_commit() { asm volatile("cp.async.commit_group;"); }
__device__ __forceinline__ void cp_wait0() { asm volatile("cp.async.wait_group 0;"); }
__device__ __forceinline__ void cp_wait2() { asm volatile("cp.async.wait_group 2;"); }

// ---------------------------------------------------------------------------
// Fused projection kernel, ONE launch, 512 CTAs.
// ---------------------------------------------------------------------------
__global__ __launch_bounds__(256) void proj_kernel(const float* __restrict__ x,
                                                   const float* __restrict__ ctx,
                                                   const float* __restrict__ Wq,
                                                   const float* __restrict__ bq,
                                                   const float* __restrict__ Wk,
                                                   const float* __restrict__ bk,
                                                   const float* __restrict__ Wv,
                                                   const float* __restrict__ bv) {
    const int tid = threadIdx.x;
    const int role = blockIdx.x >> 8;
    const int idx = blockIdx.x & 255;
    const int b = idx >> 7;
    const int n0 = (idx & 127) * 32;
    const float LOG2E = 1.4426950408889634f;

    if (role == 0) {
        __shared__ float sx[64][36];
        __shared__ float sct[64][36];
        __shared__ float sW[16][64];
        __shared__ float sb[16];

        for (int i = tid; i < 512; i += 256) {
            sW[i >> 6][i & 63] = Wq[i] * LOG2E;
            sW[8 + (i >> 6)][i & 63] = Wk[i];
        }
        if (tid < 8) { sb[tid] = bq[tid] * LOG2E; sb[8 + tid] = bk[tid]; }
#pragma unroll
        for (int k = 0; k < 2; k++) {
            int i = k * 256 + tid;
            int r = i >> 3, f4 = (i & 7) * 4;
            *(float4*)&sx[r][f4] = *(const float4*)&x[((size_t)b * CC + r) * NN + n0 + f4];
            *(float4*)&sct[r][f4] = *(const float4*)&ctx[((size_t)b * CC + r) * NN + n0 + f4];
        }
        __syncthreads();

        const int n = tid & 31;
        const int og = tid >> 5;
        const bool isk = og >= 4;
        const int r2 = 2 * (og & 3);
        const int wrow = (isk ? 8 : 0) + r2;
        float a0 = sb[wrow], a1 = sb[wrow + 1];
#pragma unroll
        for (int c = 0; c < 64; c++) {
            float v = isk ? sct[c][n] : sx[c][n];
            a0 = fmaf(sW[wrow][c], v, a0);
            a1 = fmaf(sW[wrow + 1][c], v, a1);
        }
        __nv_bfloat16* dst = isk ? g_kh : g_qh;
        *(u32*)(dst + ((size_t)b * NN + n0 + n) * 8 + r2) = packbf(a0, a1);
    } else {
        __shared__ float sC[64][36];
        __shared__ float sWv[64][68];
        __shared__ float sbv[64];

        for (int i = tid; i < 4096; i += 256) sWv[i & 63][i >> 6] = Wv[i];
        if (tid < 64) sbv[tid] = bv[tid];
#pragma unroll
        for (int k = 0; k < 2; k++) {
            int i = k * 256 + tid;
            int r = i >> 3, f4 = (i & 7) * 4;
            *(float4*)&sC[r][f4] = *(const float4*)&ctx[((size_t)b * CC + r) * NN + n0 + f4];
        }
        __syncthreads();

        const int m2 = (tid & 15) * 2;
        const int cg = (tid >> 4) * 4;
        float acc[4][2];
#pragma unroll
        for (int j = 0; j < 4; j++) acc[j][0] = acc[j][1] = sbv[cg + j];
#pragma unroll
        for (int cc = 0; cc < 64; cc++) {
            float2 vm = *(const float2*)&sC[cc][m2];
            float4 wv = *(const float4*)&sWv[cc][cg];
            float ww[4] = {wv.x, wv.y, wv.z, wv.w};
#pragma unroll
            for (int j = 0; j < 4; j++) {
                acc[j][0] = fmaf(ww[j], vm.x, acc[j][0]);
                acc[j][1] = fmaf(ww[j], vm.y, acc[j][1]);
            }
        }
#pragma unroll
        for (int j = 0; j < 4; j++)
            *(u32*)(g_vh + ((size_t)b * CC + cg + j) * NN + n0 + m2) = packbf(acc[j][0], acc[j][1]);
    }
}

// ---------------------------------------------------------------------------
// Attention: bf16 mma, 4-stage cp.async ring (wait_group 2), hoisted S-mmas.
//   grid (64 qtiles, B, 2), 256 threads = 8 warps, 2 CTAs/SM.
// ---------------------------------------------------------------------------
__global__ __launch_bounds__(256, 2) void attn_kernel(const float* __restrict__ x,
                                                      const float* __restrict__ gammap,
                                                      float* __restrict__ out) {
    __shared__ __nv_bfloat16 sQ[64][8];
    __shared__ __nv_bfloat16 sK[4][64][8];
    __shared__ __align__(16) char svbuf[4][64 * 144];   // sV 4-stage ring / sO alias
    __shared__ float sRS[64][2];
    __shared__ float sInv[64];
    __shared__ int sFlag;
    float (*sO)[65] = (float (*)[65])svbuf;

    const int tid = threadIdx.x;
    const int b = blockIdx.y;
    const int q0 = blockIdx.x * 64;
    const int s = blockIdx.z;
    const int ck0 = s * 32;
    const int w = tid >> 5;
    const int lane = tid & 31;
    const int g = lane >> 2;
    const int t = lane & 3;
    const int qT = w & 3;
    const int h = w >> 2;
    const int r = 16 * qT + g;

    const char* gk = (const char*)g_kh + (size_t)b * NN * 8 * 2;
    const char* gv = (const char*)g_vh + (size_t)b * CC * NN * 2;

    ((u32*)sQ)[tid] = ((const u32*)((const char*)g_qh + ((size_t)b * NN + q0) * 16))[tid];

    // shared-space addresses
    const u32 svb = (u32)__cvta_generic_to_shared(svbuf);
    const u32 skb = (u32)__cvta_generic_to_shared(sK);
    const u32 vA = svb + lane * 144 + 64 * h;        // ldmatrix: c = lane,    m base 32h
    const u32 vB = vA + 32 * 144;                    //           c = 32+lane
    const u32 kA = skb + (32 * h + lane) * 16;       //           m = 32h+lane
    // cp.async dst/src fixed per thread
    const u32 kDst = skb + tid * 4;
    const u32 vDst = svb + (tid >> 2) * 144 + (tid & 3) * 32;
    const char* kSrc = gk + tid * 4;
    const char* vSrc = gv + ((size_t)(tid >> 2) * NN) * 2 + (tid & 3) * 32;

    // Prologue: stage chunks ck0, ck0+1, ck0+2 into buffers 0,1,2
#pragma unroll
    for (int p = 0; p < 3; p++) {
        size_t off = (size_t)(ck0 + p) * 64;
        cp4(kDst + p * 1024, kSrc + off * 16);
        cp16(vDst + p * 9216, vSrc + off * 2);
        cp16(vDst + p * 9216 + 16, vSrc + off * 2 + 16);
        cp_commit();
    }

    // sQ is written cross-warp (warp w reads words stored by other warps):
    // MUST barrier before reading Q fragments. (R9 bug: this was missing.)
    __syncthreads();

    const u32 qa0 = *(const u32*)((const char*)sQ + r * 16 + t * 4);
    const u32 qa1 = *(const u32*)((const char*)sQ + (r + 8) * 16 + t * 4);

    float oC[8][4];
#pragma unroll
    for (int i = 0; i < 8; i++)
#pragma unroll
        for (int j = 0; j < 4; j++) oC[i][j] = 0.0f;
    float rs0 = 0.0f, rs1 = 0.0f;

    for (int ck = 0; ck < 32; ck++) {
        const int buf = ck & 3;
        const u32 vOff = buf * 9216;
        const u32 kOff = buf * 1024;

        // Wait until chunk ck's group is resident (2 groups of slack), sync.
        if (ck < 30) cp_wait2(); else cp_wait0();
        __syncthreads();

        // Stage chunk ck+3 into buffer (ck+3)&3 (freed at ck-1, barrier above)
        if (ck < 29) {
            size_t off = (size_t)(ck0 + ck + 3) * 64;
            const u32 nb = (ck + 3) & 3;
            cp4(kDst + nb * 1024, kSrc + off * 16);
            cp16(vDst + nb * 9216, vSrc + off * 2);
            cp16(vDst + nb * 9216 + 16, vSrc + off * 2 + 16);
            cp_commit();
        }

        // K b-frags + all 4 S-mmas up front (independent -> fill tensor queue)
        u32 kb[4];
        ldsm_x4(kb[0], kb[1], kb[2], kb[3], kA + kOff);
        float e[4][4];
#pragma unroll
        for (int j = 0; j < 4; j++) {
            e[j][0] = e[j][1] = e[j][2] = e[j][3] = 0.0f;
            mma_bf16_k8(e[j], qa0, qa1, kb[j]);
        }

        // ---- per-ks: V ldsm, ex2, O-mmas ----
#pragma unroll
        for (int ks = 0; ks < 2; ks++) {
            u32 bl[4][2], bh[4][2];
            {
                u32 base = vOff + 32 * ks;
                ldsm_x4(bl[0][0], bl[1][0], bl[2][0], bl[3][0], vA + base);
                ldsm_x4(bl[0][1], bl[1][1], bl[2][1], bl[3][1], vA + base + 16);
                ldsm_x4(bh[0][0], bh[1][0], bh[2][0], bh[3][0], vB + base);
                ldsm_x4(bh[0][1], bh[1][1], bh[2][1], bh[3][1], vB + base + 16);
            }
            float* e0 = e[2 * ks];
            float* e1 = e[2 * ks + 1];
            float p00 = ex2(e0[0]), p01 = ex2(e0[1]);
            float p02 = ex2(e0[2]), p03 = ex2(e0[3]);
            float p10 = ex2(e1[0]), p11 = ex2(e1[1]);
            float p12 = ex2(e1[2]), p13 = ex2(e1[3]);
            rs0 += p00 + p01 + p10 + p11;
            rs1 += p02 + p03 + p12 + p13;
            u32 a0 = packbf(p00, p01);
            u32 a1 = packbf(p02, p03);
            u32 a2 = packbf(p10, p11);
            u32 a3 = packbf(p12, p13);

#pragma unroll
            for (int cT = 0; cT < 4; cT++)
                mma_bf16_k16(oC[cT], a0, a1, a2, a3, bl[cT][0], bl[cT][1]);
#pragma unroll
            for (int cT = 0; cT < 4; cT++)
                mma_bf16_k16(oC[4 + cT], a0, a1, a2, a3, bh[cT][0], bh[cT][1]);
        }
    }

    // Rowsums
    rs0 += __shfl_xor_sync(0xffffffffu, rs0, 1);
    rs0 += __shfl_xor_sync(0xffffffffu, rs0, 2);
    rs1 += __shfl_xor_sync(0xffffffffu, rs1, 1);
    rs1 += __shfl_xor_sync(0xffffffffu, rs1, 2);
    if (t == 0) {
        sRS[r][h] = rs0;
        sRS[r + 8][h] = rs1;
    }
    __syncthreads();   // all compute done; sV ring dead; sO may be written

    // Cross-h O reduce into sO
    if (h == 0) {
#pragma unroll
        for (int cT = 0; cT < 8; cT++) {
            int c = 8 * cT + 2 * t;
            sO[r][c] = oC[cT][0];
            sO[r][c + 1] = oC[cT][1];
            sO[r + 8][c] = oC[cT][2];
            sO[r + 8][c + 1] = oC[cT][3];
        }
    }
    __syncthreads();
    if (h == 1) {
#pragma unroll
        for (int cT = 0; cT < 8; cT++) {
            int c = 8 * cT + 2 * t;
            sO[r][c] += oC[cT][0];
            sO[r][c + 1] += oC[cT][1];
            sO[r + 8][c] += oC[cT][2];
            sO[r + 8][c + 1] += oC[cT][3];
        }
    }
    __syncthreads();

    // Partial rowsum + partial bf16 O [s][b][c][n]
    if (tid < 64)
        g_prs[((size_t)s * BB + b) * NN + q0 + tid] = sRS[tid][0] + sRS[tid][1];
    {
        u32* po = (u32*)g_po + ((size_t)s * BB + b) * (CC * NN / 2);
#pragma unroll
        for (int k = 0; k < 8; k++) {
            int i = k * 256 + tid;
            int c = i >> 5, n2 = i & 31;
            po[(size_t)c * (NN / 2) + q0 / 2 + n2] = packbf(sO[2 * n2][c], sO[2 * n2 + 1][c]);
        }
    }

    // Ticket: last CTA of this (tile, b) performs the combine
    __threadfence();
    __syncthreads();
    if (tid == 0) sFlag = ((atomicAdd(&g_tk[b * 64 + blockIdx.x], 1) & (MSPLIT - 1)) == MSPLIT - 1);
    __syncthreads();

    if (sFlag) {
        __threadfence();
        if (tid < 64) {
            float rsum = 0.0f;
#pragma unroll
            for (int ss = 0; ss < MSPLIT; ss++)
                rsum += g_prs[((size_t)ss * BB + b) * NN + q0 + tid];
            sInv[tid] = gammap[0] / rsum;
        }
        __syncthreads();
#pragma unroll
        for (int k = 0; k < 8; k++) {
            int i = k * 256 + tid;
            int c = i >> 5, n2 = i & 31;
            size_t pi = (size_t)c * (NN / 2) + q0 / 2 + n2;
            float vx = 0.0f, vy = 0.0f;
#pragma unroll
            for (int ss = 0; ss < MSPLIT; ss++) {
                float2 v = unpackbf(((const u32*)g_po + ((size_t)ss * BB + b) * (CC * NN / 2))[pi]);
                vx += v.x;
                vy += v.y;
            }
            size_t gi = ((size_t)b * CC + c) * NN + q0 + 2 * n2;
            float2 xv = *(const float2*)&x[gi];
            float2 res;
            res.x = fmaf(vx, sInv[2 * n2], xv.x);
            res.y = fmaf(vy, sInv[2 * n2 + 1], xv.y);
            *(float2*)&out[gi] = res;
        }
    }
}

extern "C" void kernel_launch(void* const* d_in, const int* in_sizes, int n_in,
                              void* d_out, int out_size) {
    const float* x     = (const float*)d_in[0];
    const float* ctx   = (const float*)d_in[1];
    const float* Wq    = (const float*)d_in[2];
    const float* bq    = (const float*)d_in[3];
    const float* Wk    = (const float*)d_in[4];
    const float* bk    = (const float*)d_in[5];
    const float* Wv    = (const float*)d_in[6];
    const float* bv    = (const float*)d_in[7];
    const float* gamma = (const float*)d_in[8];
    float* out = (float*)d_out;

    proj_kernel<<<512, 256>>>(x, ctx, Wq, bq, Wk, bk, Wv, bv);
    attn_kernel<<<dim3(64, BB, MSPLIT), 256>>>(x, gamma, out);
}